// round 9
// baseline (speedup 1.0000x reference)
#include <cuda_runtime.h>

#define BB   4
#define NN   8192
#define CCH  64
#define NPTS (BB*NN)          // 32768
#define KLn  12
#define EPSbn 1e-5f
#define G_STAT 1024
#define G_CONV 1184
#define MT   96               // conv2 edge-tile (divisible by 6 and 12)
#define BKT  1024             // x-buckets per batch
#define XLO  (-5.0f)
#define BWID (10.0f/1024.0f)
#define INVBW (1024.0f/10.0f)

// ---------------- scratch (static device arrays; no allocation) ----------------
__device__ __align__(16) float  g_xt[NPTS*CCH];            // x transposed (B,N,C)   8MB
__device__ __align__(16) float4 g_pp[NPTS];                // packed points (x,y,z,|p|^2)
__device__ __align__(16) float4 g_pb[NPTS];                // bucket-sorted points
__device__             int    g_pidx[NPTS];                // bucketed -> orig n
__device__             int    g_bcnt[BB*BKT];              // bucket counts
__device__             int    g_bfill[BB*BKT];             // bucket fill cursors
__device__             int    g_boff[BB*(BKT+1)];          // bucket offsets (per batch)
__device__             int    g_idx[NPTS*KLn];             // 12 NN per point (sorted)
__device__ __align__(16) unsigned long long g_kk[26*NPTS]; // packed (d,idx) keys, 2x13 slots
__device__ __align__(16) float g_PQ[4][NPTS*CCH];          // P_s,Q_s,P_l,Q_l        32MB
__device__ __align__(16) float g_mx[NPTS*CCH];             // per-(pt,ch) max of h2   8MB
__device__ __align__(16) float g_mn[NPTS*CCH];             // per-(pt,ch) min of h2   8MB
__device__             float  g_part[2048*128];            // block partial stats
__device__             float  g_bnA[128];                  // layer1 scale/shift
__device__             float  g_bnB[128];                  // layer2 scale/shift
__device__ __align__(16) float g_Wf[4][4096];              // folded conv1 W, [k][o]
__device__ __align__(16) float g_W2t[2][4096];             // conv2 W transposed [k][o]

// ---------------- f32x2 helpers ----------------
__device__ __forceinline__ unsigned long long pk2(float lo, float hi) {
    unsigned long long r;
    asm("mov.b64 %0, {%1,%2};" : "=l"(r) : "f"(lo), "f"(hi));
    return r;
}
__device__ __forceinline__ unsigned long long dup2(float v) { return pk2(v, v); }
__device__ __forceinline__ void upk2(unsigned long long r, float& lo, float& hi) {
    asm("mov.b64 {%0,%1}, %2;" : "=f"(lo), "=f"(hi) : "l"(r));
}
__device__ __forceinline__ unsigned long long ffma2(unsigned long long a,
                                                    unsigned long long b,
                                                    unsigned long long c) {
    unsigned long long d;
    asm("fma.rn.f32x2 %0, %1, %2, %3;" : "=l"(d) : "l"(a), "l"(b), "l"(c));
    return d;
}

// monotone float->u32 (total order preserving, handles negatives)
__device__ __forceinline__ unsigned fmono(float f) {
    unsigned u = __float_as_uint(f);
    return u ^ ((u >> 31) ? 0xFFFFFFFFu : 0x80000000u);
}
__device__ __forceinline__ int xbucket(float x) {
    int bi = (int)floorf((x - XLO) * INVBW);
    return min(BKT-1, max(0, bi));
}

// ---------------- weight prep: fold conv1, transpose everything ----------------
__global__ void k_prep(const float* __restrict__ Ws1, const float* __restrict__ Wl1,
                       const float* __restrict__ Ws2, const float* __restrict__ Wl2)
{
    int t = blockIdx.x*blockDim.x + threadIdx.x;
    if (t < 4096) {
        int o = t >> 6, c = t & 63;
        float a0 = Ws1[o*128 + c],  a1 = Ws1[o*128 + 64 + c];
        g_Wf[0][c*64+o] = a0 - a1;          // Wa_s
        g_Wf[1][c*64+o] = a1;               // Wb_s
        float b0 = Wl1[o*128 + c],  b1 = Wl1[o*128 + 64 + c];
        g_Wf[2][c*64+o] = b0 - b1;          // Wa_l
        g_Wf[3][c*64+o] = b1;               // Wb_l
        g_W2t[0][c*64+o] = Ws2[o*64+c];
        g_W2t[1][c*64+o] = Wl2[o*64+c];
    }
}

// ---------------- pack pos into float4 ----------------
__global__ void k_pos(const float* __restrict__ pos)
{
    int t = blockIdx.x*blockDim.x + threadIdx.x;
    if (t < NPTS) {
        int n = t & (NN-1), b = t >> 13;
        float px = pos[(b*3+0)*NN + n];
        float py = pos[(b*3+1)*NN + n];
        float pz = pos[(b*3+2)*NN + n];
        g_pp[t] = make_float4(px, py, pz, px*px + py*py + pz*pz);
    }
}

// ---------------- coalesced tiled transpose of x ----------------
__global__ __launch_bounds__(256) void k_pack(const float* __restrict__ x)
{
    __shared__ float tile[32][33];
    int b  = blockIdx.z;
    int c0 = blockIdx.y * 32;
    int n0 = blockIdx.x * 32;
    int tx = threadIdx.x & 31, ty = threadIdx.x >> 5;   // ty 0..7
#pragma unroll
    for (int i = 0; i < 4; i++) {
        int r = ty + 8*i;                               // channel row
        tile[r][tx] = x[((size_t)(b*CCH + c0 + r))*NN + n0 + tx];
    }
    __syncthreads();
#pragma unroll
    for (int i = 0; i < 4; i++) {
        int r = ty + 8*i;                               // n row
        g_xt[((size_t)(b*NN + n0 + r))*64 + c0 + tx] = tile[tx][r];
    }
}

// ---------------- bucketing: zero, count, scan, fill ----------------
__global__ void k_bzero()
{
    int t = blockIdx.x*blockDim.x + threadIdx.x;
    if (t < BB*BKT) { g_bcnt[t] = 0; g_bfill[t] = 0; }
}
__global__ void k_bcount()
{
    int t = blockIdx.x*blockDim.x + threadIdx.x;
    if (t < NPTS) {
        int b = t >> 13;
        atomicAdd(&g_bcnt[b*BKT + xbucket(g_pp[t].x)], 1);
    }
}
__global__ __launch_bounds__(BKT) void k_bscan()
{
    __shared__ int sm[BKT];
    int b = blockIdx.x, t = threadIdx.x;
    sm[t] = g_bcnt[b*BKT + t];
    __syncthreads();
    for (int off = 1; off < BKT; off <<= 1) {
        int v = (t >= off) ? sm[t-off] : 0;
        __syncthreads();
        sm[t] += v;
        __syncthreads();
    }
    g_boff[b*(BKT+1) + t + 1] = sm[t];       // inclusive -> shifted = exclusive
    if (t == 0) g_boff[b*(BKT+1)] = 0;
}
__global__ void k_bfill()
{
    int t = blockIdx.x*blockDim.x + threadIdx.x;
    if (t < NPTS) {
        int b = t >> 13, n = t & (NN-1);
        float4 p = g_pp[t];
        int bi = xbucket(p.x);
        int pos = g_boff[b*(BKT+1) + bi] + atomicAdd(&g_bfill[b*BKT + bi], 1);
        g_pb[b*NN + pos]   = p;
        g_pidx[b*NN + pos] = n;
    }
}

// ---------------- KNN: exact slab-pruned scan over x-buckets ----------------
// 2 threads per query: h=0 scans own bucket + leftward, h=1 scans rightward.
// Register chain of 13 (dist,idx) pairs in the SHIFTED metric d~ = d^2 - |q|^2.
// Prune when edge^2 - |q|^2 >= 13th best (certified: d~ >= edge^2 - |q|^2).
#define GINS(dv, jv)                                                  \
    if ((dv) < bd12 && (jv) != p) {                                   \
        float tt = (dv); int ti = (jv);                               \
        _Pragma("unroll")                                             \
        for (int s2 = 0; s2 < 13; s2++) {                             \
            bool sw = tt < bd[s2];                                    \
            float fl = sw ? tt : bd[s2];                              \
            float fh = sw ? bd[s2] : tt;                              \
            int   il = sw ? ti : bi_[s2];                             \
            int   ih = sw ? bi_[s2] : ti;                             \
            bd[s2] = fl; tt = fh; bi_[s2] = il; ti = ih;              \
        }                                                             \
        bd12 = bd[12];                                                \
    }

__global__ __launch_bounds__(128) void k_knn1g()
{
    int t  = threadIdx.x;
    int ql = t & 63, h = t >> 6;
    int p  = blockIdx.x*64 + ql;               // bucketed global position
    int b  = p >> 13;
    float4 qp = g_pb[p];
    int selfn = g_pidx[p];
    float qx = -2.f*qp.x, qy = -2.f*qp.y, qz = -2.f*qp.z;
    int bq = xbucket(qp.x);
    const int* boff = &g_boff[b*(BKT+1)];
    int pbase = b*NN;

    float bd[13]; int bi_[13];
#pragma unroll
    for (int i = 0; i < 13; i++) { bd[i] = 3.4e38f; bi_[i] = 0; }
    float bd12 = 3.4e38f;

    int bi   = h ? bq + 1 : bq;
    int step = h ? 1 : -1;
#pragma unroll 1
    while (bi >= 0 && bi < BKT) {
        // minimal |dx| to any point in bucket bi (0/neg for own bucket)
        float edge = h ? ((XLO + bi*BWID) - qp.x)
                       : (qp.x - (XLO + (bi+1)*BWID));
        // METRIC FIX: bd holds d^2 - |q|^2; compare in the same shifted metric.
        if (edge > 0.f && fmaf(edge, edge, -qp.w) >= bd12) break;
        int s = pbase + boff[bi];
        int e = pbase + boff[bi+1];
        int j = s;
#pragma unroll 1
        for (; j + 4 <= e; j += 4) {
            float4 c0 = g_pb[j],   c1 = g_pb[j+1];
            float4 c2 = g_pb[j+2], c3 = g_pb[j+3];
            float d0 = fmaf(qx,c0.x, fmaf(qy,c0.y, fmaf(qz,c0.z, c0.w)));
            float d1 = fmaf(qx,c1.x, fmaf(qy,c1.y, fmaf(qz,c1.z, c1.w)));
            float d2 = fmaf(qx,c2.x, fmaf(qy,c2.y, fmaf(qz,c2.z, c2.w)));
            float d3 = fmaf(qx,c3.x, fmaf(qy,c3.y, fmaf(qz,c3.z, c3.w)));
            float m = fminf(fminf(d0,d1), fminf(d2,d3));
            if (m < bd12) {
                GINS(d0, j); GINS(d1, j+1); GINS(d2, j+2); GINS(d3, j+3);
            }
        }
#pragma unroll 1
        for (; j < e; j++) {
            float4 c = g_pb[j];
            float d = fmaf(qx,c.x, fmaf(qy,c.y, fmaf(qz,c.z, c.w)));
            GINS(d, j);
        }
        bi += step;
    }

    // emit 13 packed keys (dist-mono | orig idx); unfilled slots sort last
    int qglob = b*NN + selfn;
#pragma unroll
    for (int r = 0; r < 13; r++) {
        int oi = g_pidx[bi_[r]];
        unsigned long long key =
            ((unsigned long long)fmono(bd[r]) << 13) | (unsigned)oi;
        g_kk[(h*13 + r)*NPTS + qglob] = key;
    }
}

// ---------------- KNN select+sort: 12 smallest of 26 keys per query --------
__global__ __launch_bounds__(256) void k_knn3()
{
    int q = blockIdx.x*256 + threadIdx.x;
    unsigned long long best[12];
#pragma unroll
    for (int r = 0; r < 12; r++) best[r] = ~0ULL;
#pragma unroll 1
    for (int r = 0; r < 26; r++) {
        unsigned long long key = g_kk[r*NPTS + q];
        if (key < best[11]) {
            unsigned long long tt = key;
#pragma unroll
            for (int j = 0; j < 12; j++) {
                unsigned long long lo = (best[j] < tt) ? best[j] : tt;
                unsigned long long hi = (best[j] < tt) ? tt : best[j];
                best[j] = lo; tt = hi;
            }
        }
    }
#pragma unroll
    for (int r = 0; r < 12; r++)
        g_idx[q*KLn + r] = (int)(best[r] & 8191u);
}

// ---------------- P/Q GEMM with f32x2 FMA ----------------
__global__ __launch_bounds__(128) void k_pq()
{
    __shared__ __align__(16) float Ws[4096];
    __shared__ __align__(16) float Us[4096];
    int w = blockIdx.y;
    int t = threadIdx.x;
    for (int i = t; i < 4096; i += 128) Ws[i] = g_Wf[w][i];

    int base = blockIdx.x * 64;
    {   // stage X tile k-major with xor swizzle
        int e = t >> 1, h = t & 1;
        const float4* src = (const float4*)&g_xt[(base + e)*64 + h*32];
        int gg = e >> 2, eo = e & 3;
#pragma unroll
        for (int c4 = 0; c4 < 8; c4++) {
            float4 v = src[c4];
            int c = h*32 + c4*4;
            Us[(c+0)*64 + ((gg ^ ((c+0)&15))<<2) + eo] = v.x;
            Us[(c+1)*64 + ((gg ^ ((c+1)&15))<<2) + eo] = v.y;
            Us[(c+2)*64 + ((gg ^ ((c+2)&15))<<2) + eo] = v.z;
            Us[(c+3)*64 + ((gg ^ ((c+3)&15))<<2) + eo] = v.w;
        }
    }
    __syncthreads();

    int tx = t & 15, ty = t >> 4;
    unsigned long long acc2[4][4];             // [oi-pair][mi]
#pragma unroll
    for (int i = 0; i < 4; i++)
#pragma unroll
        for (int j = 0; j < 4; j++) acc2[i][j] = 0ULL;

#pragma unroll 8
    for (int k = 0; k < 64; k++) {
        const unsigned long long* ap = (const unsigned long long*)&Ws[k*64 + ty*8];
        unsigned long long a2[4] = {ap[0], ap[1], ap[2], ap[3]};
        float4 bf = *(const float4*)&Us[k*64 + ((tx ^ (k&15))<<2)];
        unsigned long long b2[4] = {dup2(bf.x), dup2(bf.y), dup2(bf.z), dup2(bf.w)};
#pragma unroll
        for (int oi = 0; oi < 4; oi++)
#pragma unroll
            for (int mi = 0; mi < 4; mi++)
                acc2[oi][mi] = ffma2(a2[oi], b2[mi], acc2[oi][mi]);
    }

    float* out = g_PQ[w];
#pragma unroll
    for (int mi = 0; mi < 4; mi++) {
        float a[8];
#pragma unroll
        for (int oi = 0; oi < 4; oi++) upk2(acc2[oi][mi], a[2*oi], a[2*oi+1]);
        int pt = base + tx*4 + mi;
        *(float4*)&out[pt*64 + ty*8]     = make_float4(a[0],a[1],a[2],a[3]);
        *(float4*)&out[pt*64 + ty*8 + 4] = make_float4(a[4],a[5],a[6],a[7]);
    }
}

// ---------------- stats of h1 = P[i]+Q[j] over all edges ----------------
template<int K>
__global__ __launch_bounds__(256) void k_stats1()
{
    const float* __restrict__ P = g_PQ[(K==6)?0:2];
    const float* __restrict__ Q = g_PQ[(K==6)?1:3];
    const int M = NPTS*K;
    int warp = threadIdx.x >> 5, lane = threadIdx.x & 31;
    int gw = blockIdx.x*8 + warp, nw = G_STAT*8;
    float s0=0, ss0=0, s1=0, ss1=0;
    for (int m = gw; m < M; m += nw) {
        int kk = m % K, bn = m / K;
        int j  = g_idx[bn*KLn + kk];
        int b  = bn >> 13;
        const float* Pp = &P[bn*64];
        const float* Qp = &Q[(b*NN + j)*64];
        float v0 = Pp[lane]      + Qp[lane];
        float v1 = Pp[lane + 32] + Qp[lane + 32];
        s0 += v0; ss0 = fmaf(v0, v0, ss0);
        s1 += v1; ss1 = fmaf(v1, v1, ss1);
    }
    __shared__ float stg[8][128];
    stg[warp][lane]      = s0;  stg[warp][64+lane] = ss0;
    stg[warp][32+lane]   = s1;  stg[warp][96+lane] = ss1;
    __syncthreads();
    int t = threadIdx.x;
    if (t < 128) {
        float a = 0;
#pragma unroll
        for (int w2 = 0; w2 < 8; w2++) a += stg[w2][t];
        g_part[blockIdx.x*128 + t] = a;
    }
}

// ---------------- finalize BN params (parallel, deterministic) ----------------
__global__ __launch_bounds__(256) void k_reduce(int G, float invM,
                         const float* __restrict__ gamma,
                         const float* __restrict__ beta, int which)
{
    __shared__ float sm[8][64];
    int t = threadIdx.x;
    int c = t & 63, grp = t >> 6;              // 4 groups
    int chunk = (G + 3) >> 2;
    int g0 = grp*chunk, g1 = min(G, g0 + chunk);
    float S = 0.f, SS = 0.f;
    for (int g = g0; g < g1; g++) { S += g_part[g*128 + c]; SS += g_part[g*128 + 64 + c]; }
    sm[grp][c] = S; sm[4+grp][c] = SS;
    __syncthreads();
    if (t < 64) {
        float Sa = 0.f, SSa = 0.f;
#pragma unroll
        for (int g = 0; g < 4; g++) { Sa += sm[g][t]; SSa += sm[4+g][t]; }
        float mean = Sa * invM;
        float var  = SSa * invM - mean*mean;
        float sc   = gamma[t] * rsqrtf(var + EPSbn);
        float sh   = beta[t] - mean*sc;
        float* dst = which ? g_bnB : g_bnA;
        dst[t] = sc; dst[64+t] = sh;
    }
}

// ---------------- conv2: 96-edge tiles, f32x2 GEMM, fused min/max over k ----------------
template<int K>
__global__ __launch_bounds__(128) void k_conv2()
{
    const float* __restrict__ P   = g_PQ[(K==6)?0:2];
    const float* __restrict__ Q   = g_PQ[(K==6)?1:3];
    const float* __restrict__ W2t = g_W2t[(K==6)?0:1];
    const int nTiles = (NPTS*K)/MT;
    const int PPT = MT/K;                      // whole points per tile

    __shared__ __align__(16) float Ws[4096];
    __shared__ __align__(16) float Ub[6336];   // union: Us 64x97 / h2s 96x66
    __shared__ float bnsc[64], bnsh[64];
    __shared__ float blockS[64], blockSS[64];
    int t = threadIdx.x;
    for (int i = t; i < 4096; i += 128) Ws[i] = W2t[i];
    if (t < 64) { bnsc[t] = g_bnA[t]; bnsh[t] = g_bnA[64+t]; }
    __syncthreads();

    int tx = t & 15, ty = t >> 4;
    float accS[8], accSS[8];
#pragma unroll
    for (int i = 0; i < 8; i++) { accS[i] = 0.f; accSS[i] = 0.f; }

    for (int tile = blockIdx.x; tile < nTiles; tile += G_CONV) {
        int mbase = tile * MT;
        __syncthreads();                       // Ub reuse guard
        // gather + BN1 + ReLU -> Us (k-major, row stride 97)
        for (int u = t; u < 2*MT; u += 128) {
            int e = u >> 1, h = u & 1;
            int m = mbase + e;
            int kk = m % K, bn = m / K;
            int j  = g_idx[bn*KLn + kk];
            int b  = bn >> 13;
            const float4* Pp = (const float4*)&P[bn*64 + h*32];
            const float4* Qp = (const float4*)&Q[(b*NN + j)*64 + h*32];
#pragma unroll
            for (int c4 = 0; c4 < 8; c4++) {
                float4 pv = Pp[c4], qv = Qp[c4];
                int c = h*32 + c4*4;
                Ub[(c+0)*97 + e] = fmaxf(0.f, fmaf(pv.x+qv.x, bnsc[c+0], bnsh[c+0]));
                Ub[(c+1)*97 + e] = fmaxf(0.f, fmaf(pv.y+qv.y, bnsc[c+1], bnsh[c+1]));
                Ub[(c+2)*97 + e] = fmaxf(0.f, fmaf(pv.z+qv.z, bnsc[c+2], bnsh[c+2]));
                Ub[(c+3)*97 + e] = fmaxf(0.f, fmaf(pv.w+qv.w, bnsc[c+3], bnsh[c+3]));
            }
        }
        __syncthreads();

        // GEMM: edges e = tx + 16*mi (mi<6), channels ty*8..ty*8+7 (as 4 pairs)
        unsigned long long acc2[4][6];
#pragma unroll
        for (int i = 0; i < 4; i++)
#pragma unroll
            for (int j2 = 0; j2 < 6; j2++) acc2[i][j2] = 0ULL;

#pragma unroll 8
        for (int k = 0; k < 64; k++) {
            const unsigned long long* ap = (const unsigned long long*)&Ws[k*64 + ty*8];
            unsigned long long a2[4] = {ap[0], ap[1], ap[2], ap[3]};
            unsigned long long b2[6];
#pragma unroll
            for (int mi = 0; mi < 6; mi++)
                b2[mi] = dup2(Ub[k*97 + tx + 16*mi]);
#pragma unroll
            for (int oi = 0; oi < 4; oi++)
#pragma unroll
                for (int mi = 0; mi < 6; mi++)
                    acc2[oi][mi] = ffma2(a2[oi], b2[mi], acc2[oi][mi]);
        }
        __syncthreads();                       // Us dead; reuse Ub for h2s

        // unpack: stats accumulation + write h2 tile to shared (row stride 66)
#pragma unroll
        for (int mi = 0; mi < 6; mi++) {
            int e = tx + 16*mi;
            float v[8];
#pragma unroll
            for (int oi = 0; oi < 4; oi++) upk2(acc2[oi][mi], v[2*oi], v[2*oi+1]);
#pragma unroll
            for (int oi = 0; oi < 8; oi++) {
                accS[oi]  += v[oi];
                accSS[oi] = fmaf(v[oi], v[oi], accSS[oi]);
            }
#pragma unroll
            for (int oi = 0; oi < 4; oi++)
                *(float2*)&Ub[e*66 + ty*8 + 2*oi] = make_float2(v[2*oi], v[2*oi+1]);
        }
        __syncthreads();

        // per-(point,channel) min/max over K edges (tile holds whole points)
        for (int s = t; s < PPT*64; s += 128) {
            int p = s >> 6, ch = s & 63;
            float vmax = -3.4e38f, vmin = 3.4e38f;
#pragma unroll
            for (int kk = 0; kk < K; kk++) {
                float v = Ub[(p*K + kk)*66 + ch];
                vmax = fmaxf(vmax, v); vmin = fminf(vmin, v);
            }
            int pt = mbase/K + p;
            g_mx[pt*64 + ch] = vmax;
            g_mn[pt*64 + ch] = vmin;
        }
    }

    // cross-thread stats reduce over tx lanes
#pragma unroll
    for (int off = 1; off < 16; off <<= 1)
#pragma unroll
        for (int oi = 0; oi < 8; oi++) {
            accS[oi]  += __shfl_xor_sync(0xffffffffu, accS[oi],  off);
            accSS[oi] += __shfl_xor_sync(0xffffffffu, accSS[oi], off);
        }
    if (tx == 0)
#pragma unroll
        for (int oi = 0; oi < 8; oi++) { blockS[ty*8+oi] = accS[oi]; blockSS[ty*8+oi] = accSS[oi]; }
    __syncthreads();
    if (t < 128)
        g_part[blockIdx.x*128 + t] = (t < 64) ? blockS[t] : blockSS[t-64];
}

// ---------------- BN2 + ReLU + max -> output (from min/max buffers) ----------------
template<int K>
__global__ __launch_bounds__(256) void k_out(float* __restrict__ out)
{
    const int chOff = (K==6) ? 0 : 64;
    __shared__ float res[64][33];
    int t = threadIdx.x;
    int warp = t >> 5, lane = t & 31;
    int bn0 = blockIdx.x * 32;
    int b = bn0 >> 13, n0 = bn0 & (NN-1);
    float sc0 = g_bnB[lane],      sh0 = g_bnB[64+lane];
    float sc1 = g_bnB[lane + 32], sh1 = g_bnB[96+lane];
#pragma unroll
    for (int i = 0; i < 4; i++) {
        int nl = warp*4 + i;
        int pt = bn0 + nl;
        float h0 = (sc0 >= 0.f) ? g_mx[pt*64 + lane]      : g_mn[pt*64 + lane];
        float h1 = (sc1 >= 0.f) ? g_mx[pt*64 + lane + 32] : g_mn[pt*64 + lane + 32];
        res[lane][nl]      = fmaxf(0.f, fmaf(h0, sc0, sh0));
        res[lane + 32][nl] = fmaxf(0.f, fmaf(h1, sc1, sh1));
    }
    __syncthreads();
#pragma unroll
    for (int i = 0; i < 8; i++) {
        int id = t + i*256;
        int r = id >> 5, col = id & 31;
        out[((size_t)b*128 + chOff + r)*NN + n0 + col] = res[r][col];
    }
}

// ---------------- launch ----------------
extern "C" void kernel_launch(void* const* d_in, const int* in_sizes, int n_in,
                              void* d_out, int out_size)
{
    const float* x    = (const float*)d_in[0];
    const float* pos  = (const float*)d_in[1];
    const float* Ws1  = (const float*)d_in[2];
    const float* gs1  = (const float*)d_in[4];
    const float* ts1  = (const float*)d_in[5];
    const float* Ws2  = (const float*)d_in[6];
    const float* gs2  = (const float*)d_in[8];
    const float* ts2  = (const float*)d_in[9];
    const float* Wl1  = (const float*)d_in[10];
    const float* gl1  = (const float*)d_in[12];
    const float* tl1  = (const float*)d_in[13];
    const float* Wl2  = (const float*)d_in[14];
    const float* gl2  = (const float*)d_in[16];
    const float* tl2  = (const float*)d_in[17];
    float* out = (float*)d_out;

    k_prep<<<16, 256>>>(Ws1, Wl1, Ws2, Wl2);
    k_pos<<<NPTS/256, 256>>>(pos);
    k_pack<<<dim3(NN/32, 2, BB), 256>>>(x);

    // bucket-pruned exact KNN
    k_bzero<<<16, 256>>>();
    k_bcount<<<NPTS/256, 256>>>();
    k_bscan<<<BB, BKT>>>();
    k_bfill<<<NPTS/256, 256>>>();
    k_knn1g<<<NPTS/64, 128>>>();
    k_knn3<<<NPTS/256, 256>>>();

    k_pq<<<dim3(NPTS/64, 4), 128>>>();

    // short stream (k=6), channels 0..63
    k_stats1<6><<<G_STAT, 256>>>();
    k_reduce<<<1, 256>>>(G_STAT, 1.f/(NPTS*6),  gs1, ts1, 0);
    k_conv2<6><<<G_CONV, 128>>>();
    k_reduce<<<1, 256>>>(G_CONV, 1.f/(NPTS*6),  gs2, ts2, 1);
    k_out<6><<<NPTS/32, 256>>>(out);

    // long stream (k=12), channels 64..127
    k_stats1<12><<<G_STAT, 256>>>();
    k_reduce<<<1, 256>>>(G_STAT, 1.f/(NPTS*12), gl1, tl1, 0);
    k_conv2<12><<<G_CONV, 128>>>();
    k_reduce<<<1, 256>>>(G_CONV, 1.f/(NPTS*12), gl2, tl2, 1);
    k_out<12><<<NPTS/32, 256>>>(out);
}

// round 10
// speedup vs baseline: 1.0693x; 1.0693x over previous
#include <cuda_runtime.h>

#define BB   4
#define NN   8192
#define CCH  64
#define NPTS (BB*NN)          // 32768
#define KLn  12
#define EPSbn 1e-5f
#define G_STAT 1024
#define G_CONV 1184
#define MT   96               // conv2 edge-tile (divisible by 6 and 12)
#define BKT  1024             // x-buckets per batch
#define XLO  (-5.0f)
#define BWID (10.0f/1024.0f)
#define INVBW (1024.0f/10.0f)
#define QB   64               // queries per knn block
#define WCH  512              // window chunk (float4s)

// ---------------- scratch (static device arrays; no allocation) ----------------
__device__ __align__(16) float  g_xt[NPTS*CCH];            // x transposed (B,N,C)   8MB
__device__ __align__(16) float4 g_pp[NPTS];                // packed points (x,y,z,|p|^2)
__device__ __align__(16) float4 g_pb[NPTS];                // bucket-sorted points
__device__             int    g_pidx[NPTS];                // bucketed pos -> orig n
__device__             int    g_p2b[NPTS];                 // bucketed pos -> bucket id
__device__             int    g_bcnt[BB*BKT];              // bucket counts
__device__             int    g_bfill[BB*BKT];             // bucket fill cursors
__device__             int    g_boff[BB*(BKT+1)];          // bucket offsets (per batch)
__device__             int    g_idx[NPTS*KLn];             // 12 NN per point (sorted)
__device__ __align__(16) unsigned long long g_kk[26*NPTS]; // packed (d,idx) keys, 2x13 slots
__device__ __align__(16) float g_PQ[4][NPTS*CCH];          // P_s,Q_s,P_l,Q_l        32MB
__device__ __align__(16) float g_mx[NPTS*CCH];             // per-(pt,ch) max of h2   8MB
__device__ __align__(16) float g_mn[NPTS*CCH];             // per-(pt,ch) min of h2   8MB
__device__             float  g_part[2048*128];            // block partial stats
__device__             float  g_bnA[128];                  // layer1 scale/shift
__device__             float  g_bnB[128];                  // layer2 scale/shift
__device__ __align__(16) float g_Wf[4][4096];              // folded conv1 W, [k][o]
__device__ __align__(16) float g_W2t[2][4096];             // conv2 W transposed [k][o]

// ---------------- f32x2 helpers ----------------
__device__ __forceinline__ unsigned long long pk2(float lo, float hi) {
    unsigned long long r;
    asm("mov.b64 %0, {%1,%2};" : "=l"(r) : "f"(lo), "f"(hi));
    return r;
}
__device__ __forceinline__ unsigned long long dup2(float v) { return pk2(v, v); }
__device__ __forceinline__ void upk2(unsigned long long r, float& lo, float& hi) {
    asm("mov.b64 {%0,%1}, %2;" : "=f"(lo), "=f"(hi) : "l"(r));
}
__device__ __forceinline__ unsigned long long ffma2(unsigned long long a,
                                                    unsigned long long b,
                                                    unsigned long long c) {
    unsigned long long d;
    asm("fma.rn.f32x2 %0, %1, %2, %3;" : "=l"(d) : "l"(a), "l"(b), "l"(c));
    return d;
}

// monotone float->u32 (total order preserving, handles negatives)
__device__ __forceinline__ unsigned fmono(float f) {
    unsigned u = __float_as_uint(f);
    return u ^ ((u >> 31) ? 0xFFFFFFFFu : 0x80000000u);
}
__device__ __forceinline__ int xbucket(float x) {
    int bi = (int)floorf((x - XLO) * INVBW);
    return min(BKT-1, max(0, bi));
}

// ---------------- weight prep: fold conv1, transpose everything ----------------
__global__ void k_prep(const float* __restrict__ Ws1, const float* __restrict__ Wl1,
                       const float* __restrict__ Ws2, const float* __restrict__ Wl2)
{
    int t = blockIdx.x*blockDim.x + threadIdx.x;
    if (t < 4096) {
        int o = t >> 6, c = t & 63;
        float a0 = Ws1[o*128 + c],  a1 = Ws1[o*128 + 64 + c];
        g_Wf[0][c*64+o] = a0 - a1;          // Wa_s
        g_Wf[1][c*64+o] = a1;               // Wb_s
        float b0 = Wl1[o*128 + c],  b1 = Wl1[o*128 + 64 + c];
        g_Wf[2][c*64+o] = b0 - b1;          // Wa_l
        g_Wf[3][c*64+o] = b1;               // Wb_l
        g_W2t[0][c*64+o] = Ws2[o*64+c];
        g_W2t[1][c*64+o] = Wl2[o*64+c];
    }
}

// ---------------- pack pos into float4 ----------------
__global__ void k_pos(const float* __restrict__ pos)
{
    int t = blockIdx.x*blockDim.x + threadIdx.x;
    if (t < NPTS) {
        int n = t & (NN-1), b = t >> 13;
        float px = pos[(b*3+0)*NN + n];
        float py = pos[(b*3+1)*NN + n];
        float pz = pos[(b*3+2)*NN + n];
        g_pp[t] = make_float4(px, py, pz, px*px + py*py + pz*pz);
    }
}

// ---------------- coalesced tiled transpose of x ----------------
__global__ __launch_bounds__(256) void k_pack(const float* __restrict__ x)
{
    __shared__ float tile[32][33];
    int b  = blockIdx.z;
    int c0 = blockIdx.y * 32;
    int n0 = blockIdx.x * 32;
    int tx = threadIdx.x & 31, ty = threadIdx.x >> 5;   // ty 0..7
#pragma unroll
    for (int i = 0; i < 4; i++) {
        int r = ty + 8*i;                               // channel row
        tile[r][tx] = x[((size_t)(b*CCH + c0 + r))*NN + n0 + tx];
    }
    __syncthreads();
#pragma unroll
    for (int i = 0; i < 4; i++) {
        int r = ty + 8*i;                               // n row
        g_xt[((size_t)(b*NN + n0 + r))*64 + c0 + tx] = tile[tx][r];
    }
}

// ---------------- bucketing: zero, count, scan, fill ----------------
__global__ void k_bzero()
{
    int t = blockIdx.x*blockDim.x + threadIdx.x;
    if (t < BB*BKT) { g_bcnt[t] = 0; g_bfill[t] = 0; }
}
__global__ void k_bcount()
{
    int t = blockIdx.x*blockDim.x + threadIdx.x;
    if (t < NPTS) {
        int b = t >> 13;
        atomicAdd(&g_bcnt[b*BKT + xbucket(g_pp[t].x)], 1);
    }
}
__global__ __launch_bounds__(BKT) void k_bscan()
{
    __shared__ int sm[BKT];
    int b = blockIdx.x, t = threadIdx.x;
    sm[t] = g_bcnt[b*BKT + t];
    __syncthreads();
    for (int off = 1; off < BKT; off <<= 1) {
        int v = (t >= off) ? sm[t-off] : 0;
        __syncthreads();
        sm[t] += v;
        __syncthreads();
    }
    g_boff[b*(BKT+1) + t + 1] = sm[t];       // inclusive -> shifted = exclusive
    if (t == 0) g_boff[b*(BKT+1)] = 0;
}
__global__ void k_bfill()
{
    int t = blockIdx.x*blockDim.x + threadIdx.x;
    if (t < NPTS) {
        int b = t >> 13, n = t & (NN-1);
        float4 p = g_pp[t];
        int bi = xbucket(p.x);
        int pos = g_boff[b*(BKT+1) + bi] + atomicAdd(&g_bfill[b*BKT + bi], 1);
        g_pb[b*NN + pos]   = p;
        g_pidx[b*NN + pos] = n;
        g_p2b[b*NN + pos]  = bi;
    }
}

// ---------------- windowed exact KNN: shared-staged, block-expanded ----------
// Block: QB consecutive bucketed queries, 128 threads (TPQ=2: h=0 left, h=1 right).
// Phase A: dist-only FMNMX top-13 in shifted metric (d~ = d^2 - |q|^2) over the
//   central span + own side, expanded chunk-by-chunk with certified bucket-edge
//   prune. Phase B: rescan final window, emit keys partitioned by position.
#define KINS(dv)                                                   \
    if ((dv) < bd[12]) {                                           \
        float tt = (dv);                                           \
        _Pragma("unroll")                                          \
        for (int jj = 0; jj < 13; jj++) {                          \
            float lo = fminf(bd[jj], tt);                          \
            tt = fmaxf(bd[jj], tt);                                \
            bd[jj] = lo;                                           \
        }                                                          \
    }

__global__ __launch_bounds__(128) void k_knnw()
{
    __shared__ __align__(16) float4 winL[WCH];
    __shared__ __align__(16) float4 winR[WCH];
    __shared__ __align__(16) float4 winC[QB];
    __shared__ int s_bL, s_bR, s_needL, s_needR;
    __shared__ float s_thr[2][QB];

    int t  = threadIdx.x;
    int ql = t & (QB-1), h = t >> 6;
    int P  = blockIdx.x*QB + ql;               // bucketed global position
    int b  = P >> 13;
    int blo = b*NN, bhi = blo + NN;
    int C0 = blockIdx.x*QB;
    float4 qp = g_pb[P];
    float qx = -2.f*qp.x, qy = -2.f*qp.y, qz = -2.f*qp.z;
    float qw = qp.w;

    if (t < QB) winC[t] = g_pb[C0 + t];
    if (t == 0) { s_bL = C0; s_bR = C0 + QB; }

    float bd[13];
#pragma unroll
    for (int i = 0; i < 13; i++) bd[i] = 3.4e38f;
    __syncthreads();

    // central span (both sides process; includes self -> slot 0)
#pragma unroll 1
    for (int c0 = 0; c0 < QB; c0 += 4) {
        float4 p0 = winC[c0+0], p1 = winC[c0+1];
        float4 p2 = winC[c0+2], p3 = winC[c0+3];
        float d0 = fmaf(qx,p0.x, fmaf(qy,p0.y, fmaf(qz,p0.z, p0.w)));
        float d1 = fmaf(qx,p1.x, fmaf(qy,p1.y, fmaf(qz,p1.z, p1.w)));
        float d2 = fmaf(qx,p2.x, fmaf(qy,p2.y, fmaf(qz,p2.z, p2.w)));
        float d3 = fmaf(qx,p3.x, fmaf(qy,p3.y, fmaf(qz,p3.z, p3.w)));
        float m = fminf(fminf(d0,d1), fminf(d2,d3));
        if (m < bd[12]) { KINS(d0); KINS(d1); KINS(d2); KINS(d3); }
    }

    bool done = false;
    // ---- phase A expansion loop (all block-uniform control) ----
    for (;;) {
        __syncthreads();                       // S1: prior win use / s_b* update
        if (t == 0) { s_needL = 0; s_needR = 0; }
        __syncthreads();                       // S2
        int bL = s_bL, bR = s_bR;
        if (!done) {
            if (h == 0) {
                if (bL <= blo) done = true;
                else {
                    float bx = XLO + (g_p2b[bL-1] + 1)*BWID;   // hi edge of next bucket
                    float dx = qp.x - bx;
                    if (dx > 0.f && fmaf(dx, dx, -qw) >= bd[12]) done = true;
                }
            } else {
                if (bR >= bhi) done = true;
                else {
                    float bx = XLO + g_p2b[bR]*BWID;           // lo edge of next bucket
                    float dx = bx - qp.x;
                    if (dx > 0.f && fmaf(dx, dx, -qw) >= bd[12]) done = true;
                }
            }
            if (!done) { if (h == 0) s_needL = 1; else s_needR = 1; }
        }
        __syncthreads();                       // S3: flags final
        int needL = s_needL, needR = s_needR;
        if (!needL && !needR) break;
        int nL = needL ? min(WCH, bL - blo) : 0;
        int nR = needR ? min(WCH, bhi - bR) : 0;
        for (int i = t; i < nL; i += 128) winL[i] = g_pb[bL - nL + i];
        for (int i = t; i < nR; i += 128) winR[i] = g_pb[bR + i];
        if (t == 0) { s_bL = bL - nL; s_bR = bR + nR; }
        __syncthreads();                       // S4: loads complete
        if (!done) {
            const float4* win = h ? winR : winL;
            int n = h ? nR : nL;
            int c0 = 0;
#pragma unroll 1
            for (; c0 + 4 <= n; c0 += 4) {
                float4 p0 = win[c0+0], p1 = win[c0+1];
                float4 p2 = win[c0+2], p3 = win[c0+3];
                float d0 = fmaf(qx,p0.x, fmaf(qy,p0.y, fmaf(qz,p0.z, p0.w)));
                float d1 = fmaf(qx,p1.x, fmaf(qy,p1.y, fmaf(qz,p1.z, p1.w)));
                float d2 = fmaf(qx,p2.x, fmaf(qy,p2.y, fmaf(qz,p2.z, p2.w)));
                float d3 = fmaf(qx,p3.x, fmaf(qy,p3.y, fmaf(qz,p3.z, p3.w)));
                float m = fminf(fminf(d0,d1), fminf(d2,d3));
                if (m < bd[12]) { KINS(d0); KINS(d1); KINS(d2); KINS(d3); }
            }
#pragma unroll 1
            for (; c0 < n; c0++) {
                float4 p = win[c0];
                float d = fmaf(qx,p.x, fmaf(qy,p.y, fmaf(qz,p.z, p.w)));
                KINS(d);
            }
        }
    }

    // ---- thr = min over both sides; final window extents ----
    s_thr[h][ql] = bd[12];
    __syncthreads();
    int LF = s_bL, RF = s_bR;
    float thr = fminf(s_thr[0][ql], s_thr[1][ql]);

    // ---- phase B: rescan window, emit keys (h=0: pos<P, h=1: pos>P) ----
    int qglob = blo + g_pidx[P];
    int cnt = 0;
#pragma unroll 1
    for (int pos0 = LF; pos0 < RF; pos0 += WCH) {
        int n = min(WCH, RF - pos0);
        __syncthreads();
        for (int i = t; i < n; i += 128) winL[i] = g_pb[pos0 + i];
        __syncthreads();
        bool rel = h ? (pos0 + n > P + 1) : (pos0 < P);
        if (rel) {
            int c0 = 0;
#pragma unroll 1
            for (; c0 + 4 <= n; c0 += 4) {
                float4 p0 = winL[c0+0], p1 = winL[c0+1];
                float4 p2 = winL[c0+2], p3 = winL[c0+3];
                float d0 = fmaf(qx,p0.x, fmaf(qy,p0.y, fmaf(qz,p0.z, p0.w)));
                float d1 = fmaf(qx,p1.x, fmaf(qy,p1.y, fmaf(qz,p1.z, p1.w)));
                float d2 = fmaf(qx,p2.x, fmaf(qy,p2.y, fmaf(qz,p2.z, p2.w)));
                float d3 = fmaf(qx,p3.x, fmaf(qy,p3.y, fmaf(qz,p3.z, p3.w)));
                float m = fminf(fminf(d0,d1), fminf(d2,d3));
                if (m <= thr) {
                    float dd[4] = {d0, d1, d2, d3};
#pragma unroll
                    for (int u = 0; u < 4; u++) {
                        int pos = pos0 + c0 + u;
                        bool side = h ? (pos > P) : (pos < P);
                        if (dd[u] <= thr && side && cnt < 13) {
                            unsigned long long key =
                                ((unsigned long long)fmono(dd[u]) << 13)
                                | (unsigned)g_pidx[pos];
                            g_kk[(h*13 + cnt)*NPTS + qglob] = key;
                            cnt++;
                        }
                    }
                }
            }
#pragma unroll 1
            for (; c0 < n; c0++) {
                float4 p = winL[c0];
                float d = fmaf(qx,p.x, fmaf(qy,p.y, fmaf(qz,p.z, p.w)));
                int pos = pos0 + c0;
                bool side = h ? (pos > P) : (pos < P);
                if (d <= thr && side && cnt < 13) {
                    unsigned long long key =
                        ((unsigned long long)fmono(d) << 13)
                        | (unsigned)g_pidx[pos];
                    g_kk[(h*13 + cnt)*NPTS + qglob] = key;
                    cnt++;
                }
            }
        }
    }
#pragma unroll 1
    for (int r = cnt; r < 13; r++)
        g_kk[(h*13 + r)*NPTS + qglob] = ~0ULL;   // pad
}

// ---------------- KNN select+sort: 12 smallest of 26 keys per query --------
__global__ __launch_bounds__(256) void k_knn3()
{
    int q = blockIdx.x*256 + threadIdx.x;
    unsigned long long best[12];
#pragma unroll
    for (int r = 0; r < 12; r++) best[r] = ~0ULL;
#pragma unroll 1
    for (int r = 0; r < 26; r++) {
        unsigned long long key = g_kk[r*NPTS + q];
        if (key < best[11]) {
            unsigned long long tt = key;
#pragma unroll
            for (int j = 0; j < 12; j++) {
                unsigned long long lo = (best[j] < tt) ? best[j] : tt;
                unsigned long long hi = (best[j] < tt) ? tt : best[j];
                best[j] = lo; tt = hi;
            }
        }
    }
#pragma unroll
    for (int r = 0; r < 12; r++)
        g_idx[q*KLn + r] = (int)(best[r] & 8191u);
}

// ---------------- P/Q GEMM with f32x2 FMA ----------------
__global__ __launch_bounds__(128) void k_pq()
{
    __shared__ __align__(16) float Ws[4096];
    __shared__ __align__(16) float Us[4096];
    int w = blockIdx.y;
    int t = threadIdx.x;
    for (int i = t; i < 4096; i += 128) Ws[i] = g_Wf[w][i];

    int base = blockIdx.x * 64;
    {   // stage X tile k-major with xor swizzle
        int e = t >> 1, h = t & 1;
        const float4* src = (const float4*)&g_xt[(base + e)*64 + h*32];
        int gg = e >> 2, eo = e & 3;
#pragma unroll
        for (int c4 = 0; c4 < 8; c4++) {
            float4 v = src[c4];
            int c = h*32 + c4*4;
            Us[(c+0)*64 + ((gg ^ ((c+0)&15))<<2) + eo] = v.x;
            Us[(c+1)*64 + ((gg ^ ((c+1)&15))<<2) + eo] = v.y;
            Us[(c+2)*64 + ((gg ^ ((c+2)&15))<<2) + eo] = v.z;
            Us[(c+3)*64 + ((gg ^ ((c+3)&15))<<2) + eo] = v.w;
        }
    }
    __syncthreads();

    int tx = t & 15, ty = t >> 4;
    unsigned long long acc2[4][4];             // [oi-pair][mi]
#pragma unroll
    for (int i = 0; i < 4; i++)
#pragma unroll
        for (int j = 0; j < 4; j++) acc2[i][j] = 0ULL;

#pragma unroll 8
    for (int k = 0; k < 64; k++) {
        const unsigned long long* ap = (const unsigned long long*)&Ws[k*64 + ty*8];
        unsigned long long a2[4] = {ap[0], ap[1], ap[2], ap[3]};
        float4 bf = *(const float4*)&Us[k*64 + ((tx ^ (k&15))<<2)];
        unsigned long long b2[4] = {dup2(bf.x), dup2(bf.y), dup2(bf.z), dup2(bf.w)};
#pragma unroll
        for (int oi = 0; oi < 4; oi++)
#pragma unroll
            for (int mi = 0; mi < 4; mi++)
                acc2[oi][mi] = ffma2(a2[oi], b2[mi], acc2[oi][mi]);
    }

    float* out = g_PQ[w];
#pragma unroll
    for (int mi = 0; mi < 4; mi++) {
        float a[8];
#pragma unroll
        for (int oi = 0; oi < 4; oi++) upk2(acc2[oi][mi], a[2*oi], a[2*oi+1]);
        int pt = base + tx*4 + mi;
        *(float4*)&out[pt*64 + ty*8]     = make_float4(a[0],a[1],a[2],a[3]);
        *(float4*)&out[pt*64 + ty*8 + 4] = make_float4(a[4],a[5],a[6],a[7]);
    }
}

// ---------------- stats of h1 = P[i]+Q[j] over all edges ----------------
template<int K>
__global__ __launch_bounds__(256) void k_stats1()
{
    const float* __restrict__ P = g_PQ[(K==6)?0:2];
    const float* __restrict__ Q = g_PQ[(K==6)?1:3];
    const int M = NPTS*K;
    int warp = threadIdx.x >> 5, lane = threadIdx.x & 31;
    int gw = blockIdx.x*8 + warp, nw = G_STAT*8;
    float s0=0, ss0=0, s1=0, ss1=0;
    for (int m = gw; m < M; m += nw) {
        int kk = m % K, bn = m / K;
        int j  = g_idx[bn*KLn + kk];
        int b  = bn >> 13;
        const float* Pp = &P[bn*64];
        const float* Qp = &Q[(b*NN + j)*64];
        float v0 = Pp[lane]      + Qp[lane];
        float v1 = Pp[lane + 32] + Qp[lane + 32];
        s0 += v0; ss0 = fmaf(v0, v0, ss0);
        s1 += v1; ss1 = fmaf(v1, v1, ss1);
    }
    __shared__ float stg[8][128];
    stg[warp][lane]      = s0;  stg[warp][64+lane] = ss0;
    stg[warp][32+lane]   = s1;  stg[warp][96+lane] = ss1;
    __syncthreads();
    int t = threadIdx.x;
    if (t < 128) {
        float a = 0;
#pragma unroll
        for (int w2 = 0; w2 < 8; w2++) a += stg[w2][t];
        g_part[blockIdx.x*128 + t] = a;
    }
}

// ---------------- finalize BN params (parallel, deterministic) ----------------
__global__ __launch_bounds__(256) void k_reduce(int G, float invM,
                         const float* __restrict__ gamma,
                         const float* __restrict__ beta, int which)
{
    __shared__ float sm[8][64];
    int t = threadIdx.x;
    int c = t & 63, grp = t >> 6;              // 4 groups
    int chunk = (G + 3) >> 2;
    int g0 = grp*chunk, g1 = min(G, g0 + chunk);
    float S = 0.f, SS = 0.f;
    for (int g = g0; g < g1; g++) { S += g_part[g*128 + c]; SS += g_part[g*128 + 64 + c]; }
    sm[grp][c] = S; sm[4+grp][c] = SS;
    __syncthreads();
    if (t < 64) {
        float Sa = 0.f, SSa = 0.f;
#pragma unroll
        for (int g = 0; g < 4; g++) { Sa += sm[g][t]; SSa += sm[4+g][t]; }
        float mean = Sa * invM;
        float var  = SSa * invM - mean*mean;
        float sc   = gamma[t] * rsqrtf(var + EPSbn);
        float sh   = beta[t] - mean*sc;
        float* dst = which ? g_bnB : g_bnA;
        dst[t] = sc; dst[64+t] = sh;
    }
}

// ---------------- conv2: 96-edge tiles, f32x2 GEMM, fused min/max over k ----------------
template<int K>
__global__ __launch_bounds__(128) void k_conv2()
{
    const float* __restrict__ P   = g_PQ[(K==6)?0:2];
    const float* __restrict__ Q   = g_PQ[(K==6)?1:3];
    const float* __restrict__ W2t = g_W2t[(K==6)?0:1];
    const int nTiles = (NPTS*K)/MT;
    const int PPT = MT/K;                      // whole points per tile

    __shared__ __align__(16) float Ws[4096];
    __shared__ __align__(16) float Ub[6336];   // union: Us 64x97 / h2s 96x66
    __shared__ float bnsc[64], bnsh[64];
    __shared__ float blockS[64], blockSS[64];
    int t = threadIdx.x;
    for (int i = t; i < 4096; i += 128) Ws[i] = W2t[i];
    if (t < 64) { bnsc[t] = g_bnA[t]; bnsh[t] = g_bnA[64+t]; }
    __syncthreads();

    int tx = t & 15, ty = t >> 4;
    float accS[8], accSS[8];
#pragma unroll
    for (int i = 0; i < 8; i++) { accS[i] = 0.f; accSS[i] = 0.f; }

    for (int tile = blockIdx.x; tile < nTiles; tile += G_CONV) {
        int mbase = tile * MT;
        __syncthreads();                       // Ub reuse guard
        // gather + BN1 + ReLU -> Us (k-major, row stride 97)
        for (int u = t; u < 2*MT; u += 128) {
            int e = u >> 1, h = u & 1;
            int m = mbase + e;
            int kk = m % K, bn = m / K;
            int j  = g_idx[bn*KLn + kk];
            int b  = bn >> 13;
            const float4* Pp = (const float4*)&P[bn*64 + h*32];
            const float4* Qp = (const float4*)&Q[(b*NN + j)*64 + h*32];
#pragma unroll
            for (int c4 = 0; c4 < 8; c4++) {
                float4 pv = Pp[c4], qv = Qp[c4];
                int c = h*32 + c4*4;
                Ub[(c+0)*97 + e] = fmaxf(0.f, fmaf(pv.x+qv.x, bnsc[c+0], bnsh[c+0]));
                Ub[(c+1)*97 + e] = fmaxf(0.f, fmaf(pv.y+qv.y, bnsc[c+1], bnsh[c+1]));
                Ub[(c+2)*97 + e] = fmaxf(0.f, fmaf(pv.z+qv.z, bnsc[c+2], bnsh[c+2]));
                Ub[(c+3)*97 + e] = fmaxf(0.f, fmaf(pv.w+qv.w, bnsc[c+3], bnsh[c+3]));
            }
        }
        __syncthreads();

        // GEMM: edges e = tx + 16*mi (mi<6), channels ty*8..ty*8+7 (as 4 pairs)
        unsigned long long acc2[4][6];
#pragma unroll
        for (int i = 0; i < 4; i++)
#pragma unroll
            for (int j2 = 0; j2 < 6; j2++) acc2[i][j2] = 0ULL;

#pragma unroll 8
        for (int k = 0; k < 64; k++) {
            const unsigned long long* ap = (const unsigned long long*)&Ws[k*64 + ty*8];
            unsigned long long a2[4] = {ap[0], ap[1], ap[2], ap[3]};
            unsigned long long b2[6];
#pragma unroll
            for (int mi = 0; mi < 6; mi++)
                b2[mi] = dup2(Ub[k*97 + tx + 16*mi]);
#pragma unroll
            for (int oi = 0; oi < 4; oi++)
#pragma unroll
                for (int mi = 0; mi < 6; mi++)
                    acc2[oi][mi] = ffma2(a2[oi], b2[mi], acc2[oi][mi]);
        }
        __syncthreads();                       // Us dead; reuse Ub for h2s

        // unpack: stats accumulation + write h2 tile to shared (row stride 66)
#pragma unroll
        for (int mi = 0; mi < 6; mi++) {
            int e = tx + 16*mi;
            float v[8];
#pragma unroll
            for (int oi = 0; oi < 4; oi++) upk2(acc2[oi][mi], v[2*oi], v[2*oi+1]);
#pragma unroll
            for (int oi = 0; oi < 8; oi++) {
                accS[oi]  += v[oi];
                accSS[oi] = fmaf(v[oi], v[oi], accSS[oi]);
            }
#pragma unroll
            for (int oi = 0; oi < 4; oi++)
                *(float2*)&Ub[e*66 + ty*8 + 2*oi] = make_float2(v[2*oi], v[2*oi+1]);
        }
        __syncthreads();

        // per-(point,channel) min/max over K edges (tile holds whole points)
        for (int s = t; s < PPT*64; s += 128) {
            int p = s >> 6, ch = s & 63;
            float vmax = -3.4e38f, vmin = 3.4e38f;
#pragma unroll
            for (int kk = 0; kk < K; kk++) {
                float v = Ub[(p*K + kk)*66 + ch];
                vmax = fmaxf(vmax, v); vmin = fminf(vmin, v);
            }
            int pt = mbase/K + p;
            g_mx[pt*64 + ch] = vmax;
            g_mn[pt*64 + ch] = vmin;
        }
    }

    // cross-thread stats reduce over tx lanes
#pragma unroll
    for (int off = 1; off < 16; off <<= 1)
#pragma unroll
        for (int oi = 0; oi < 8; oi++) {
            accS[oi]  += __shfl_xor_sync(0xffffffffu, accS[oi],  off);
            accSS[oi] += __shfl_xor_sync(0xffffffffu, accSS[oi], off);
        }
    if (tx == 0)
#pragma unroll
        for (int oi = 0; oi < 8; oi++) { blockS[ty*8+oi] = accS[oi]; blockSS[ty*8+oi] = accSS[oi]; }
    __syncthreads();
    if (t < 128)
        g_part[blockIdx.x*128 + t] = (t < 64) ? blockS[t] : blockSS[t-64];
}

// ---------------- BN2 + ReLU + max -> output (from min/max buffers) ----------------
template<int K>
__global__ __launch_bounds__(256) void k_out(float* __restrict__ out)
{
    const int chOff = (K==6) ? 0 : 64;
    __shared__ float res[64][33];
    int t = threadIdx.x;
    int warp = t >> 5, lane = t & 31;
    int bn0 = blockIdx.x * 32;
    int b = bn0 >> 13, n0 = bn0 & (NN-1);
    float sc0 = g_bnB[lane],      sh0 = g_bnB[64+lane];
    float sc1 = g_bnB[lane + 32], sh1 = g_bnB[96+lane];
#pragma unroll
    for (int i = 0; i < 4; i++) {
        int nl = warp*4 + i;
        int pt = bn0 + nl;
        float h0 = (sc0 >= 0.f) ? g_mx[pt*64 + lane]      : g_mn[pt*64 + lane];
        float h1 = (sc1 >= 0.f) ? g_mx[pt*64 + lane + 32] : g_mn[pt*64 + lane + 32];
        res[lane][nl]      = fmaxf(0.f, fmaf(h0, sc0, sh0));
        res[lane + 32][nl] = fmaxf(0.f, fmaf(h1, sc1, sh1));
    }
    __syncthreads();
#pragma unroll
    for (int i = 0; i < 8; i++) {
        int id = t + i*256;
        int r = id >> 5, col = id & 31;
        out[((size_t)b*128 + chOff + r)*NN + n0 + col] = res[r][col];
    }
}

// ---------------- launch ----------------
extern "C" void kernel_launch(void* const* d_in, const int* in_sizes, int n_in,
                              void* d_out, int out_size)
{
    const float* x    = (const float*)d_in[0];
    const float* pos  = (const float*)d_in[1];
    const float* Ws1  = (const float*)d_in[2];
    const float* gs1  = (const float*)d_in[4];
    const float* ts1  = (const float*)d_in[5];
    const float* Ws2  = (const float*)d_in[6];
    const float* gs2  = (const float*)d_in[8];
    const float* ts2  = (const float*)d_in[9];
    const float* Wl1  = (const float*)d_in[10];
    const float* gl1  = (const float*)d_in[12];
    const float* tl1  = (const float*)d_in[13];
    const float* Wl2  = (const float*)d_in[14];
    const float* gl2  = (const float*)d_in[16];
    const float* tl2  = (const float*)d_in[17];
    float* out = (float*)d_out;

    k_prep<<<16, 256>>>(Ws1, Wl1, Ws2, Wl2);
    k_pos<<<NPTS/256, 256>>>(pos);
    k_pack<<<dim3(NN/32, 2, BB), 256>>>(x);

    // bucket sort + windowed exact KNN
    k_bzero<<<16, 256>>>();
    k_bcount<<<NPTS/256, 256>>>();
    k_bscan<<<BB, BKT>>>();
    k_bfill<<<NPTS/256, 256>>>();
    k_knnw<<<NPTS/QB, 128>>>();
    k_knn3<<<NPTS/256, 256>>>();

    k_pq<<<dim3(NPTS/64, 4), 128>>>();

    // short stream (k=6), channels 0..63
    k_stats1<6><<<G_STAT, 256>>>();
    k_reduce<<<1, 256>>>(G_STAT, 1.f/(NPTS*6),  gs1, ts1, 0);
    k_conv2<6><<<G_CONV, 128>>>();
    k_reduce<<<1, 256>>>(G_CONV, 1.f/(NPTS*6),  gs2, ts2, 1);
    k_out<6><<<NPTS/32, 256>>>(out);

    // long stream (k=12), channels 64..127
    k_stats1<12><<<G_STAT, 256>>>();
    k_reduce<<<1, 256>>>(G_STAT, 1.f/(NPTS*12), gl1, tl1, 0);
    k_conv2<12><<<G_CONV, 128>>>();
    k_reduce<<<1, 256>>>(G_CONV, 1.f/(NPTS*12), gl2, tl2, 1);
    k_out<12><<<NPTS/32, 256>>>(out);
}